// round 8
// baseline (speedup 1.0000x reference)
#include <cuda_runtime.h>
#include <cstddef>
#include <cstdint>

#define NN 100000
#define DD 128

__device__ float g_agg[(size_t)NN * DD];
__device__ float g_x1 [(size_t)NN * DD];
__device__ float g_x2 [(size_t)NN * DD];
__device__ float g_inv[NN];
__device__ int   g_cnt[NN];

typedef unsigned long long ull;

// ---------------------------------------------------------------------------
__global__ void deg_kernel(const int* __restrict__ dst, int e) {
    int i = blockIdx.x * blockDim.x + threadIdx.x;
    if (i < e) atomicAdd(&g_cnt[dst[i]], 1);
}

__global__ void inv_kernel(int n) {
    int i = blockIdx.x * blockDim.x + threadIdx.x;
    if (i < n) g_inv[i] = 1.0f / fmaxf((float)g_cnt[i], 1.0f);
}

// ---------------------------------------------------------------------------
__global__ void scatter_kernel(const float* __restrict__ x,
                               const int* __restrict__ src,
                               const int* __restrict__ dst, int e) {
    int w    = (blockIdx.x * blockDim.x + threadIdx.x) >> 5;
    int lane = threadIdx.x & 31;
    if (w >= e) return;
    int s = __ldg(src + w);
    int d = __ldg(dst + w);
    float4 v = *(const float4*)(x + (size_t)s * DD + lane * 4);
    atomicAdd((float4*)(g_agg + (size_t)d * DD + lane * 4), v);
}

// ---------------------------------------------------------------------------
// Packed dual-GEMM SAGE layer, 1024 threads (occ 50%), 4 rows/warp,
// TILE_ROWS=128, split-K staging, paired-k interleaved weights so one
// LDS.128 yields (wl,wr) for k and k+1 at one column.
//   out = act( (agg*inv) @ Wl + b + xin @ Wr )
// ---------------------------------------------------------------------------
#define TILE_ROWS 128
#define KHALF 64
#define GEMM_THREADS 1024
// bytes: Wi paired 128*128*8 = 131072, AXs 128*64*8 = 65536, bias 512
#define SM_W    0
#define SM_A    131072
#define SM_BIAS (131072 + 65536)
#define GEMM_SMEM_BYTES (SM_BIAS + 512)

__device__ __forceinline__ void ffma2(ull& d, ull a, ull b) {
    asm volatile("fma.rn.f32x2 %0, %1, %2, %0;" : "+l"(d) : "l"(a), "l"(b));
}

__global__ __launch_bounds__(GEMM_THREADS, 1)
void sage_gemm_kernel(const float* __restrict__ agg,
                      const float* __restrict__ xin,
                      const float* __restrict__ Wl,
                      const float* __restrict__ bias,
                      const float* __restrict__ Wr,
                      float* __restrict__ out,
                      int n, int do_relu) {
    extern __shared__ char smem[];
    const int tid = threadIdx.x;

    // Build paired-k interleaved weights once per persistent block:
    // ull at SM_W + ((k>>1)*128 + c)*16 + (k&1)*8  holds (Wl[k][c], Wr[k][c])
    for (int i = tid; i < DD * DD; i += GEMM_THREADS) {
        int k = i >> 7, c = i & 127;
        float2 p = make_float2(Wl[i], Wr[i]);
        *(ull*)(smem + SM_W + (size_t)(((k >> 1) * 128 + c) * 16 + (k & 1) * 8))
            = *(ull*)&p;
    }
    if (tid < DD) ((float*)(smem + SM_BIAS))[tid] = bias[tid];

    const int lane = tid & 31;   // base column
    const int wid  = tid >> 5;   // 0..31
    const int r0   = wid * 4;    // rows r0..r0+3

    const int ntiles = (n + TILE_ROWS - 1) / TILE_ROWS;
    for (int t = blockIdx.x; t < ntiles; t += gridDim.x) {
        const int base = t * TILE_ROWS;

        ull acc[4][4];
        #pragma unroll
        for (int r = 0; r < 4; r++)
            #pragma unroll
            for (int j = 0; j < 4; j++) acc[r][j] = 0ull;

        #pragma unroll
        for (int h = 0; h < 2; h++) {
            const int k0 = h * KHALF;
            __syncthreads();   // previous AXs consumption done
            // Stage (a,x) pairs for k in [k0, k0+64)
            for (int i = tid; i < TILE_ROWS * 16; i += GEMM_THREADS) {
                int row = i >> 4, kk4 = (i & 15) * 4;
                int gr = base + row;
                if (gr < n) {
                    float inv = g_inv[gr];
                    float4 a = *(const float4*)(agg + (size_t)gr * DD + k0 + kk4);
                    float4 x = *(const float4*)(xin + (size_t)gr * DD + k0 + kk4);
                    a.x *= inv; a.y *= inv; a.z *= inv; a.w *= inv;
                    float4* d4 = (float4*)(smem + SM_A + (size_t)(row * KHALF + kk4) * 8);
                    d4[0] = make_float4(a.x, x.x, a.y, x.y);
                    d4[1] = make_float4(a.z, x.z, a.w, x.w);
                }
            }
            __syncthreads();

            const char* Wb = smem + SM_W + (size_t)h * 65536; // 32 k-pairs
            #pragma unroll 2
            for (int kp = 0; kp < KHALF / 2; kp++) {
                // 4 cols per thread: one LDS.128 each -> (w_k, w_k1)
                ulonglong2 w[4];
                #pragma unroll
                for (int j = 0; j < 4; j++)
                    w[j] = *(const ulonglong2*)
                        (Wb + (size_t)(kp * 128 + lane + 32 * j) * 16);
                #pragma unroll
                for (int r = 0; r < 4; r++) {
                    // broadcast 16B: (a,x) for k and k+1 of this row
                    ulonglong2 ax = *(const ulonglong2*)
                        (smem + SM_A + (size_t)((r0 + r) * KHALF + kp * 2) * 8);
                    #pragma unroll
                    for (int j = 0; j < 4; j++) {
                        ffma2(acc[r][j], ax.x, w[j].x);
                        ffma2(acc[r][j], ax.y, w[j].y);
                    }
                }
            }
        }

        // Epilogue: fold (accA + accX) + bias, optional relu
        #pragma unroll
        for (int r = 0; r < 4; r++) {
            int gr = base + r0 + r;
            if (gr < n) {
                #pragma unroll
                for (int j = 0; j < 4; j++) {
                    int c = lane + 32 * j;
                    float2 v = *(float2*)&acc[r][j];
                    float s = v.x + v.y + ((const float*)(smem + SM_BIAS))[c];
                    if (do_relu) s = fmaxf(s, 0.f);
                    out[(size_t)gr * DD + c] = s;
                }
            }
        }
    }
}

// ---------------------------------------------------------------------------
__global__ void predict_kernel(const int* __restrict__ s,
                               const int* __restrict__ d,
                               const float* __restrict__ Wlin,
                               const float* __restrict__ blin,
                               float* __restrict__ out, int L) {
    int w    = (blockIdx.x * blockDim.x + threadIdx.x) >> 5;
    int lane = threadIdx.x & 31;
    if (w >= L) return;
    int si = __ldg(s + w);
    int di = __ldg(d + w);
    float4 a  = *(const float4*)(g_x2 + (size_t)si * DD + lane * 4);
    float4 b  = *(const float4*)(g_x2 + (size_t)di * DD + lane * 4);
    float4 w0 = *(const float4*)(Wlin + lane * 4);
    float4 w1 = *(const float4*)(Wlin + DD + lane * 4);
    float acc = a.x * w0.x + a.y * w0.y + a.z * w0.z + a.w * w0.w
              + b.x * w1.x + b.y * w1.y + b.z * w1.z + b.w * w1.w;
    #pragma unroll
    for (int o = 16; o > 0; o >>= 1)
        acc += __shfl_down_sync(0xFFFFFFFFu, acc, o);
    if (lane == 0) out[w] = acc + __ldg(blin);
}

// ---------------------------------------------------------------------------
extern "C" void kernel_launch(void* const* d_in, const int* in_sizes, int n_in,
                              void* d_out, int out_size) {
    const int*   ei   = (const int*)d_in[0];
    const int*   eli  = (const int*)d_in[1];
    const float* emb  = (const float*)d_in[2];
    const float* W1l  = (const float*)d_in[3];
    const float* b1   = (const float*)d_in[4];
    const float* W1r  = (const float*)d_in[5];
    const float* W2l  = (const float*)d_in[6];
    const float* b2   = (const float*)d_in[7];
    const float* W2r  = (const float*)d_in[8];
    const float* Wlin = (const float*)d_in[9];
    const float* blin = (const float*)d_in[10];
    float*       out  = (float*)d_out;

    const int E = in_sizes[0] / 2;
    const int L = in_sizes[1] / 2;
    const int N = in_sizes[2] / DD;

    const int* src = ei;
    const int* dst = ei + E;
    const int* ls  = eli;
    const int* ld  = eli + L;

    void* p_agg = nullptr; cudaGetSymbolAddress(&p_agg, g_agg);
    void* p_cnt = nullptr; cudaGetSymbolAddress(&p_cnt, g_cnt);
    float* x1 = nullptr; cudaGetSymbolAddress((void**)&x1, g_x1);
    float* x2 = nullptr; cudaGetSymbolAddress((void**)&x2, g_x2);
    float* agg = (float*)p_agg;

    cudaFuncSetAttribute(sage_gemm_kernel,
                         cudaFuncAttributeMaxDynamicSharedMemorySize,
                         GEMM_SMEM_BYTES);

    const int scatter_blocks = ((size_t)E * 32 + 255) / 256;
    const int gemm_grid = 148;

    cudaMemsetAsync(p_cnt, 0, sizeof(int) * (size_t)N);
    cudaMemsetAsync(p_agg, 0, sizeof(float) * (size_t)N * DD);
    deg_kernel<<<(E + 255) / 256, 256>>>(dst, E);
    inv_kernel<<<(N + 255) / 256, 256>>>(N);

    scatter_kernel<<<scatter_blocks, 256>>>(emb, src, dst, E);
    sage_gemm_kernel<<<gemm_grid, GEMM_THREADS, GEMM_SMEM_BYTES>>>(
        agg, emb, W1l, b1, W1r, x1, N, 1);

    cudaMemsetAsync(p_agg, 0, sizeof(float) * (size_t)N * DD);
    scatter_kernel<<<scatter_blocks, 256>>>(x1, src, dst, E);
    sage_gemm_kernel<<<gemm_grid, GEMM_THREADS, GEMM_SMEM_BYTES>>>(
        agg, x1, W2l, b2, W2r, x2, N, 0);

    predict_kernel<<<((size_t)L * 32 + 127) / 128, 128>>>(ls, ld, Wlin, blin, out, L);
}

// round 9
// speedup vs baseline: 1.5763x; 1.5763x over previous
#include <cuda_runtime.h>
#include <cstddef>
#include <cstdint>

#define NN 100000
#define DD 128

__device__ float g_agg[(size_t)NN * DD];
__device__ float g_x1 [(size_t)NN * DD];
__device__ float g_r0 [NN];
__device__ float g_r1 [NN];
__device__ float g_inv[NN];
__device__ int   g_cnt[NN];
__device__ float g_u0[DD], g_u1[DD], g_v0[DD], g_v1[DD];
__device__ float g_c;

typedef unsigned long long ull;

// ---------------------------------------------------------------------------
__global__ void deg_kernel(const int* __restrict__ dst, int e) {
    int i = blockIdx.x * blockDim.x + threadIdx.x;
    if (i < e) atomicAdd(&g_cnt[dst[i]], 1);
}

__global__ void inv_kernel(int n) {
    int i = blockIdx.x * blockDim.x + threadIdx.x;
    if (i < n) g_inv[i] = 1.0f / fmaxf((float)g_cnt[i], 1.0f);
}

// ---------------------------------------------------------------------------
__global__ void scatter_kernel(const float* __restrict__ x,
                               const int* __restrict__ src,
                               const int* __restrict__ dst, int e) {
    int w    = (blockIdx.x * blockDim.x + threadIdx.x) >> 5;
    int lane = threadIdx.x & 31;
    if (w >= e) return;
    int s = __ldg(src + w);
    int d = __ldg(dst + w);
    float4 v = *(const float4*)(x + (size_t)s * DD + lane * 4);
    atomicAdd((float4*)(g_agg + (size_t)d * DD + lane * 4), v);
}

// ---------------------------------------------------------------------------
// Layer-1 packed dual-GEMM (best measured config, R5):
//   x1 = relu( (agg*inv) @ W1l + b1 + emb @ W1r )
// ---------------------------------------------------------------------------
#define TILE_ROWS 64
#define GEMM_THREADS 512
#define GEMM_SMEM_FLOATS (32768 + 16384 + 128)
#define GEMM_SMEM_BYTES  (GEMM_SMEM_FLOATS * 4)

__device__ __forceinline__ void ffma2(ull& d, ull a, ull b) {
    asm volatile("fma.rn.f32x2 %0, %1, %2, %0;" : "+l"(d) : "l"(a), "l"(b));
}

__global__ __launch_bounds__(GEMM_THREADS, 1)
void sage_gemm_kernel(const float* __restrict__ agg,
                      const float* __restrict__ xin,
                      const float* __restrict__ Wl,
                      const float* __restrict__ bias,
                      const float* __restrict__ Wr,
                      float* __restrict__ out,
                      int n, int do_relu) {
    extern __shared__ float sm[];
    float* Wi  = sm;                       // [128][128] float2 pairs (wl,wr)
    float* AXs = Wi + 32768;               // [64][128] float2 pairs (a,x)
    float* bs  = AXs + TILE_ROWS * DD * 2; // [128]

    const int tid = threadIdx.x;

    for (int i = tid; i < 4096; i += GEMM_THREADS) {
        float4 l = ((const float4*)Wl)[i];
        float4 r = ((const float4*)Wr)[i];
        ((float4*)Wi)[i * 2 + 0] = make_float4(l.x, r.x, l.y, r.y);
        ((float4*)Wi)[i * 2 + 1] = make_float4(l.z, r.z, l.w, r.w);
    }
    if (tid < DD) bs[tid] = bias[tid];
    __syncthreads();

    const int lane = tid & 31;
    const int rg   = tid >> 5;
    const int r0   = rg * 4;

    const int ntiles = (n + TILE_ROWS - 1) / TILE_ROWS;
    for (int t = blockIdx.x; t < ntiles; t += gridDim.x) {
        const int base = t * TILE_ROWS;

        for (int i = tid; i < TILE_ROWS * 32; i += GEMM_THREADS) {
            int row = i >> 5, c4 = i & 31;
            int gr = base + row;
            if (gr < n) {
                float inv = g_inv[gr];
                float4 a = ((const float4*)(agg + (size_t)gr * DD))[c4];
                float4 x = ((const float4*)(xin + (size_t)gr * DD))[c4];
                a.x *= inv; a.y *= inv; a.z *= inv; a.w *= inv;
                float4* dst4 = (float4*)(AXs + (row * DD + c4 * 4) * 2);
                dst4[0] = make_float4(a.x, x.x, a.y, x.y);
                dst4[1] = make_float4(a.z, x.z, a.w, x.w);
            }
        }
        __syncthreads();

        ull acc[4][4];
        #pragma unroll
        for (int r = 0; r < 4; r++)
            #pragma unroll
            for (int j = 0; j < 4; j++) acc[r][j] = 0ull;

        const ull* Wiu = (const ull*)Wi;
        const ull* AXu = (const ull*)AXs;

        #pragma unroll 4
        for (int k = 0; k < DD; k += 2) {
            ull w0[4], w1[4];
            #pragma unroll
            for (int j = 0; j < 4; j++) {
                w0[j] = Wiu[(k    ) * DD + lane + 32 * j];
                w1[j] = Wiu[(k + 1) * DD + lane + 32 * j];
            }
            #pragma unroll
            for (int r = 0; r < 4; r++) {
                ulonglong2 ax = *(const ulonglong2*)(AXu + (r0 + r) * DD + k);
                #pragma unroll
                for (int j = 0; j < 4; j++) {
                    ffma2(acc[r][j], ax.x, w0[j]);
                    ffma2(acc[r][j], ax.y, w1[j]);
                }
            }
        }

        #pragma unroll
        for (int r = 0; r < 4; r++) {
            int gr = base + r0 + r;
            if (gr < n) {
                #pragma unroll
                for (int j = 0; j < 4; j++) {
                    int c = lane + 32 * j;
                    float2 v = *(float2*)&acc[r][j];
                    float s = v.x + v.y + bs[c];
                    if (do_relu) s = fmaxf(s, 0.f);
                    out[(size_t)gr * DD + c] = s;
                }
            }
        }
        __syncthreads();
    }
}

// ---------------------------------------------------------------------------
// Precompute u/v projection vectors + constant:
//   u0 = W2l @ w0, u1 = W2l @ w1, v0 = W2r @ w0, v1 = W2r @ w1
//   c  = b2·(w0+w1) + blin
// One block, 128 threads; thread i handles row i.
// ---------------------------------------------------------------------------
__global__ void uv_kernel(const float* __restrict__ W2l,
                          const float* __restrict__ W2r,
                          const float* __restrict__ b2,
                          const float* __restrict__ Wlin,
                          const float* __restrict__ blin) {
    __shared__ float w0s[DD], w1s[DD];
    int i = threadIdx.x;
    w0s[i] = Wlin[i];
    w1s[i] = Wlin[DD + i];
    __syncthreads();
    float u0 = 0.f, u1 = 0.f, v0 = 0.f, v1 = 0.f;
    const float* rl = W2l + (size_t)i * DD;
    const float* rr = W2r + (size_t)i * DD;
    #pragma unroll 4
    for (int j = 0; j < DD; j++) {
        float a = rl[j], b = rr[j];
        u0 = fmaf(a, w0s[j], u0);
        u1 = fmaf(a, w1s[j], u1);
        v0 = fmaf(b, w0s[j], v0);
        v1 = fmaf(b, w1s[j], v1);
    }
    g_u0[i] = u0; g_u1[i] = u1; g_v0[i] = v0; g_v1[i] = v1;
    if (i == 0) {
        float c = blin[0];
        for (int j = 0; j < DD; j++)
            c = fmaf(b2[j], w0s[j] + w1s[j], c);
        g_c = c;
    }
}

// ---------------------------------------------------------------------------
// Per-node fold: r0[v] = inv[v]*(sum2[v]·u0) + x1[v]·v0   (r1 likewise)
// One warp per node.
// ---------------------------------------------------------------------------
__global__ void node_dot_kernel(int n) {
    int v    = (blockIdx.x * blockDim.x + threadIdx.x) >> 5;
    int lane = threadIdx.x & 31;
    if (v >= n) return;
    float inv = g_inv[v];
    float4 s = *(const float4*)(g_agg + (size_t)v * DD + lane * 4);
    float4 x = *(const float4*)(g_x1  + (size_t)v * DD + lane * 4);
    float4 u0 = *(const float4*)(g_u0 + lane * 4);
    float4 u1 = *(const float4*)(g_u1 + lane * 4);
    float4 v0 = *(const float4*)(g_v0 + lane * 4);
    float4 v1 = *(const float4*)(g_v1 + lane * 4);
    float su0 = s.x * u0.x + s.y * u0.y + s.z * u0.z + s.w * u0.w;
    float su1 = s.x * u1.x + s.y * u1.y + s.z * u1.z + s.w * u1.w;
    float xv0 = x.x * v0.x + x.y * v0.y + x.z * v0.z + x.w * v0.w;
    float xv1 = x.x * v1.x + x.y * v1.y + x.z * v1.z + x.w * v1.w;
    float p0 = inv * su0 + xv0;
    float p1 = inv * su1 + xv1;
    #pragma unroll
    for (int o = 16; o > 0; o >>= 1) {
        p0 += __shfl_down_sync(0xFFFFFFFFu, p0, o);
        p1 += __shfl_down_sync(0xFFFFFFFFu, p1, o);
    }
    if (lane == 0) { g_r0[v] = p0; g_r1[v] = p1; }
}

// ---------------------------------------------------------------------------
// Predict: out[l] = r0[s[l]] + r1[d[l]] + c
// ---------------------------------------------------------------------------
__global__ void predict_kernel(const int* __restrict__ s,
                               const int* __restrict__ d,
                               float* __restrict__ out, int L) {
    int l = blockIdx.x * blockDim.x + threadIdx.x;
    if (l >= L) return;
    out[l] = g_r0[__ldg(s + l)] + g_r1[__ldg(d + l)] + g_c;
}

// ---------------------------------------------------------------------------
extern "C" void kernel_launch(void* const* d_in, const int* in_sizes, int n_in,
                              void* d_out, int out_size) {
    const int*   ei   = (const int*)d_in[0];
    const int*   eli  = (const int*)d_in[1];
    const float* emb  = (const float*)d_in[2];
    const float* W1l  = (const float*)d_in[3];
    const float* b1   = (const float*)d_in[4];
    const float* W1r  = (const float*)d_in[5];
    const float* W2l  = (const float*)d_in[6];
    const float* b2   = (const float*)d_in[7];
    const float* W2r  = (const float*)d_in[8];
    const float* Wlin = (const float*)d_in[9];
    const float* blin = (const float*)d_in[10];
    float*       out  = (float*)d_out;

    const int E = in_sizes[0] / 2;
    const int L = in_sizes[1] / 2;
    const int N = in_sizes[2] / DD;

    const int* src = ei;
    const int* dst = ei + E;
    const int* ls  = eli;
    const int* ld  = eli + L;

    void* p_agg = nullptr; cudaGetSymbolAddress(&p_agg, g_agg);
    void* p_cnt = nullptr; cudaGetSymbolAddress(&p_cnt, g_cnt);
    float* x1 = nullptr; cudaGetSymbolAddress((void**)&x1, g_x1);
    float* agg = (float*)p_agg;

    cudaFuncSetAttribute(sage_gemm_kernel,
                         cudaFuncAttributeMaxDynamicSharedMemorySize,
                         GEMM_SMEM_BYTES);

    const int scatter_blocks = ((size_t)E * 32 + 255) / 256;
    const int gemm_grid = 148;

    cudaMemsetAsync(p_cnt, 0, sizeof(int) * (size_t)N);
    cudaMemsetAsync(p_agg, 0, sizeof(float) * (size_t)N * DD);
    deg_kernel<<<(E + 255) / 256, 256>>>(dst, E);
    inv_kernel<<<(N + 255) / 256, 256>>>(N);

    // u/v projections (independent of graph work — launch early)
    uv_kernel<<<1, DD>>>(W2l, W2r, b2, Wlin, blin);

    // Layer 1
    scatter_kernel<<<scatter_blocks, 256>>>(emb, src, dst, E);
    sage_gemm_kernel<<<gemm_grid, GEMM_THREADS, GEMM_SMEM_BYTES>>>(
        agg, emb, W1l, b1, W1r, x1, N, 1);

    // Layer 2 aggregation only (GEMM folded into u/v projections)
    cudaMemsetAsync(p_agg, 0, sizeof(float) * (size_t)N * DD);
    scatter_kernel<<<scatter_blocks, 256>>>(x1, src, dst, E);

    // Fold per node, then predict
    node_dot_kernel<<<((size_t)N * 32 + 255) / 256, 256>>>(N);
    predict_kernel<<<(L + 255) / 256, 256>>>(ls, ld, out, L);
}

// round 10
// speedup vs baseline: 1.9455x; 1.2342x over previous
#include <cuda_runtime.h>
#include <cstddef>
#include <cstdint>

#define NN 100000
#define DD 128

__device__ float g_agg[(size_t)NN * DD];   // layer-1 neighbor sums
__device__ float g_q0 [NN], g_q1 [NN];     // x1·u0, x1·u1
__device__ float g_xv0[NN], g_xv1[NN];     // x1·v0, x1·v1
__device__ float g_aq0[NN], g_aq1[NN];     // scattered q sums
__device__ float g_r0 [NN], g_r1 [NN];
__device__ float g_inv[NN];
__device__ int   g_cnt[NN];
__device__ float g_u0[DD], g_u1[DD], g_v0[DD], g_v1[DD];
__device__ float g_c;

typedef unsigned long long ull;

// ---------------------------------------------------------------------------
__global__ void deg_kernel(const int* __restrict__ dst, int e) {
    int i = blockIdx.x * blockDim.x + threadIdx.x;
    if (i < e) atomicAdd(&g_cnt[dst[i]], 1);
}

__global__ void inv_kernel(int n) {
    int i = blockIdx.x * blockDim.x + threadIdx.x;
    if (i < n) g_inv[i] = 1.0f / fmaxf((float)g_cnt[i], 1.0f);
}

// ---------------------------------------------------------------------------
__global__ void scatter_kernel(const float* __restrict__ x,
                               const int* __restrict__ src,
                               const int* __restrict__ dst, int e) {
    int w    = (blockIdx.x * blockDim.x + threadIdx.x) >> 5;
    int lane = threadIdx.x & 31;
    if (w >= e) return;
    int s = __ldg(src + w);
    int d = __ldg(dst + w);
    float4 v = *(const float4*)(x + (size_t)s * DD + lane * 4);
    atomicAdd((float4*)(g_agg + (size_t)d * DD + lane * 4), v);
}

// ---------------------------------------------------------------------------
// Scalar scatter for layer 2: aq0[d] += q0[s], aq1[d] += q1[s]
// ---------------------------------------------------------------------------
__global__ void scatter2_kernel(const int* __restrict__ src,
                                const int* __restrict__ dst, int e) {
    int i = blockIdx.x * blockDim.x + threadIdx.x;
    if (i >= e) return;
    int s = __ldg(src + i);
    int d = __ldg(dst + i);
    atomicAdd(&g_aq0[d], g_q0[s]);
    atomicAdd(&g_aq1[d], g_q1[s]);
}

// ---------------------------------------------------------------------------
// Precompute u/v projection vectors + constant:
//   u0 = W2l @ w0, u1 = W2l @ w1, v0 = W2r @ w0, v1 = W2r @ w1
//   c  = b2·(w0+w1) + blin
// ---------------------------------------------------------------------------
__global__ void uv_kernel(const float* __restrict__ W2l,
                          const float* __restrict__ W2r,
                          const float* __restrict__ b2,
                          const float* __restrict__ Wlin,
                          const float* __restrict__ blin) {
    __shared__ float w0s[DD], w1s[DD];
    int i = threadIdx.x;
    w0s[i] = Wlin[i];
    w1s[i] = Wlin[DD + i];
    __syncthreads();
    float u0 = 0.f, u1 = 0.f, v0 = 0.f, v1 = 0.f;
    const float* rl = W2l + (size_t)i * DD;
    const float* rr = W2r + (size_t)i * DD;
    #pragma unroll 4
    for (int j = 0; j < DD; j++) {
        float a = rl[j], b = rr[j];
        u0 = fmaf(a, w0s[j], u0);
        u1 = fmaf(a, w1s[j], u1);
        v0 = fmaf(b, w0s[j], v0);
        v1 = fmaf(b, w1s[j], v1);
    }
    g_u0[i] = u0; g_u1[i] = u1; g_v0[i] = v0; g_v1[i] = v1;
    if (i == 0) {
        float c = blin[0];
        for (int j = 0; j < DD; j++)
            c = fmaf(b2[j], w0s[j] + w1s[j], c);
        g_c = c;
    }
}

// ---------------------------------------------------------------------------
// Layer-1 packed dual-GEMM fused with projection epilogue:
//   x1row = relu( (agg*inv) @ W1l + b1 + emb @ W1r )     (registers only)
//   q0 = x1row·u0, q1 = x1row·u1, xv0 = x1row·v0, xv1 = x1row·v1
// x1 is never written to global memory.
// ---------------------------------------------------------------------------
#define TILE_ROWS 64
#define GEMM_THREADS 512
#define GEMM_SMEM_FLOATS (32768 + 16384 + 128)
#define GEMM_SMEM_BYTES  (GEMM_SMEM_FLOATS * 4)

__device__ __forceinline__ void ffma2(ull& d, ull a, ull b) {
    asm volatile("fma.rn.f32x2 %0, %1, %2, %0;" : "+l"(d) : "l"(a), "l"(b));
}

__global__ __launch_bounds__(GEMM_THREADS, 1)
void sage_gemm_fused(const float* __restrict__ agg,
                     const float* __restrict__ xin,
                     const float* __restrict__ Wl,
                     const float* __restrict__ bias,
                     const float* __restrict__ Wr,
                     int n) {
    extern __shared__ float sm[];
    float* Wi  = sm;                       // [128][128] float2 pairs (wl,wr)
    float* AXs = Wi + 32768;               // [64][128] float2 pairs (a,x)
    float* bs  = AXs + TILE_ROWS * DD * 2; // [128]

    const int tid = threadIdx.x;

    for (int i = tid; i < 4096; i += GEMM_THREADS) {
        float4 l = ((const float4*)Wl)[i];
        float4 r = ((const float4*)Wr)[i];
        ((float4*)Wi)[i * 2 + 0] = make_float4(l.x, r.x, l.y, r.y);
        ((float4*)Wi)[i * 2 + 1] = make_float4(l.z, r.z, l.w, r.w);
    }
    if (tid < DD) bs[tid] = bias[tid];

    const int lane = tid & 31;
    const int rg   = tid >> 5;
    const int r0   = rg * 4;

    // Projection vectors at this thread's 4 columns
    float u0r[4], u1r[4], v0r[4], v1r[4];
    #pragma unroll
    for (int j = 0; j < 4; j++) {
        int c = lane + 32 * j;
        u0r[j] = g_u0[c]; u1r[j] = g_u1[c];
        v0r[j] = g_v0[c]; v1r[j] = g_v1[c];
    }
    __syncthreads();

    const int ntiles = (n + TILE_ROWS - 1) / TILE_ROWS;
    for (int t = blockIdx.x; t < ntiles; t += gridDim.x) {
        const int base = t * TILE_ROWS;

        for (int i = tid; i < TILE_ROWS * 32; i += GEMM_THREADS) {
            int row = i >> 5, c4 = i & 31;
            int gr = base + row;
            if (gr < n) {
                float inv = g_inv[gr];
                float4 a = ((const float4*)(agg + (size_t)gr * DD))[c4];
                float4 x = ((const float4*)(xin + (size_t)gr * DD))[c4];
                a.x *= inv; a.y *= inv; a.z *= inv; a.w *= inv;
                float4* dst4 = (float4*)(AXs + (row * DD + c4 * 4) * 2);
                dst4[0] = make_float4(a.x, x.x, a.y, x.y);
                dst4[1] = make_float4(a.z, x.z, a.w, x.w);
            }
        }
        __syncthreads();

        ull acc[4][4];
        #pragma unroll
        for (int r = 0; r < 4; r++)
            #pragma unroll
            for (int j = 0; j < 4; j++) acc[r][j] = 0ull;

        const ull* Wiu = (const ull*)Wi;
        const ull* AXu = (const ull*)AXs;

        #pragma unroll 4
        for (int k = 0; k < DD; k += 2) {
            ull w0[4], w1[4];
            #pragma unroll
            for (int j = 0; j < 4; j++) {
                w0[j] = Wiu[(k    ) * DD + lane + 32 * j];
                w1[j] = Wiu[(k + 1) * DD + lane + 32 * j];
            }
            #pragma unroll
            for (int r = 0; r < 4; r++) {
                ulonglong2 ax = *(const ulonglong2*)(AXu + (r0 + r) * DD + k);
                #pragma unroll
                for (int j = 0; j < 4; j++) {
                    ffma2(acc[r][j], ax.x, w0[j]);
                    ffma2(acc[r][j], ax.y, w1[j]);
                }
            }
        }

        // Epilogue: relu then project onto u0/u1/v0/v1, warp-reduce per row
        #pragma unroll
        for (int r = 0; r < 4; r++) {
            int gr = base + r0 + r;
            float p0 = 0.f, p1 = 0.f, p2 = 0.f, p3 = 0.f;
            #pragma unroll
            for (int j = 0; j < 4; j++) {
                int c = lane + 32 * j;
                float2 v = *(float2*)&acc[r][j];
                float s = fmaxf(v.x + v.y + bs[c], 0.f);
                p0 = fmaf(s, u0r[j], p0);
                p1 = fmaf(s, u1r[j], p1);
                p2 = fmaf(s, v0r[j], p2);
                p3 = fmaf(s, v1r[j], p3);
            }
            #pragma unroll
            for (int o = 16; o > 0; o >>= 1) {
                p0 += __shfl_down_sync(0xFFFFFFFFu, p0, o);
                p1 += __shfl_down_sync(0xFFFFFFFFu, p1, o);
                p2 += __shfl_down_sync(0xFFFFFFFFu, p2, o);
                p3 += __shfl_down_sync(0xFFFFFFFFu, p3, o);
            }
            if (lane == 0 && gr < n) {
                g_q0 [gr] = p0;
                g_q1 [gr] = p1;
                g_xv0[gr] = p2;
                g_xv1[gr] = p3;
            }
        }
        __syncthreads();
    }
}

// ---------------------------------------------------------------------------
// Fold: r0[v] = inv[v]*aq0[v] + xv0[v]   (r1 likewise)
// ---------------------------------------------------------------------------
__global__ void fold_kernel(int n) {
    int v = blockIdx.x * blockDim.x + threadIdx.x;
    if (v >= n) return;
    float inv = g_inv[v];
    g_r0[v] = fmaf(inv, g_aq0[v], g_xv0[v]);
    g_r1[v] = fmaf(inv, g_aq1[v], g_xv1[v]);
}

// ---------------------------------------------------------------------------
// Predict: out[l] = r0[s[l]] + r1[d[l]] + c
// ---------------------------------------------------------------------------
__global__ void predict_kernel(const int* __restrict__ s,
                               const int* __restrict__ d,
                               float* __restrict__ out, int L) {
    int l = blockIdx.x * blockDim.x + threadIdx.x;
    if (l >= L) return;
    out[l] = g_r0[__ldg(s + l)] + g_r1[__ldg(d + l)] + g_c;
}

// ---------------------------------------------------------------------------
extern "C" void kernel_launch(void* const* d_in, const int* in_sizes, int n_in,
                              void* d_out, int out_size) {
    const int*   ei   = (const int*)d_in[0];
    const int*   eli  = (const int*)d_in[1];
    const float* emb  = (const float*)d_in[2];
    const float* W1l  = (const float*)d_in[3];
    const float* b1   = (const float*)d_in[4];
    const float* W1r  = (const float*)d_in[5];
    const float* W2l  = (const float*)d_in[6];
    const float* b2   = (const float*)d_in[7];
    const float* W2r  = (const float*)d_in[8];
    const float* Wlin = (const float*)d_in[9];
    const float* blin = (const float*)d_in[10];
    float*       out  = (float*)d_out;

    const int E = in_sizes[0] / 2;
    const int L = in_sizes[1] / 2;
    const int N = in_sizes[2] / DD;

    const int* src = ei;
    const int* dst = ei + E;
    const int* ls  = eli;
    const int* ld  = eli + L;

    void* p_agg = nullptr; cudaGetSymbolAddress(&p_agg, g_agg);
    void* p_cnt = nullptr; cudaGetSymbolAddress(&p_cnt, g_cnt);
    void* p_aq0 = nullptr; cudaGetSymbolAddress(&p_aq0, g_aq0);
    void* p_aq1 = nullptr; cudaGetSymbolAddress(&p_aq1, g_aq1);
    float* agg = (float*)p_agg;

    cudaFuncSetAttribute(sage_gemm_fused,
                         cudaFuncAttributeMaxDynamicSharedMemorySize,
                         GEMM_SMEM_BYTES);

    const int scatter_blocks = ((size_t)E * 32 + 255) / 256;

    // Setup
    cudaMemsetAsync(p_cnt, 0, sizeof(int) * (size_t)N);
    cudaMemsetAsync(p_agg, 0, sizeof(float) * (size_t)N * DD);
    cudaMemsetAsync(p_aq0, 0, sizeof(float) * (size_t)N);
    cudaMemsetAsync(p_aq1, 0, sizeof(float) * (size_t)N);
    deg_kernel<<<(E + 255) / 256, 256>>>(dst, E);
    inv_kernel<<<(N + 255) / 256, 256>>>(N);
    uv_kernel<<<1, DD>>>(W2l, W2r, b2, Wlin, blin);

    // Layer 1 aggregation + fused GEMM/projection (x1 never materialized)
    scatter_kernel<<<scatter_blocks, 256>>>(emb, src, dst, E);
    sage_gemm_fused<<<148, GEMM_THREADS, GEMM_SMEM_BYTES>>>(
        agg, emb, W1l, b1, W1r, N);

    // Layer 2 collapses to scalar scatter + fold
    scatter2_kernel<<<(E + 255) / 256, 256>>>(src, dst, E);
    fold_kernel<<<(N + 255) / 256, 256>>>(N);
    predict_kernel<<<(L + 255) / 256, 256>>>(ls, ld, out, L);
}